// round 4
// baseline (speedup 1.0000x reference)
#include <cuda_runtime.h>
#include <cstdint>

#define H        256
#define FOURH    1024
#define NG       2048
#define APG      64
#define GRIDA    296          // 2 CTAs per SM
#define TILE_B   (APG*H*4)    // 65536 bytes per graph tile

// ---------------- device scratch ----------------
__device__ float g_Wc[FOURH * H];
__device__ float g_bc[FOURH];
__device__ float g_q0[H];
__device__ float g_c0[H];
__device__ float g_c [NG * H];
__device__ float g_h [NG * H];
__device__ float g_gates[NG * FOURH];

__device__ __forceinline__ float sigmoidf_(float v) {
    return 1.0f / (1.0f + __expf(-v));
}

// ---------------- prep ----------------
__global__ void prep_kernel(const float* __restrict__ W_ih,
                            const float* __restrict__ W_hh,
                            const float* __restrict__ b_ih,
                            const float* __restrict__ b_hh) {
    int idx = blockIdx.x * 256 + threadIdx.x;
    if (idx < FOURH * H) g_Wc[idx] = W_ih[idx] + W_hh[idx];
    if (idx < FOURH)     g_bc[idx] = b_ih[idx] + b_hh[idx];
    if (idx < H) {
        float gi = b_ih[idx]       + b_hh[idx];
        float gg = b_ih[512 + idx] + b_hh[512 + idx];
        float go = b_ih[768 + idx] + b_hh[768 + idx];
        float c  = sigmoidf_(gi) * tanhf(gg);
        g_c0[idx] = c;
        g_q0[idx] = sigmoidf_(go) * tanhf(c);
    }
}

// ---------------- packed f32x2 helpers ----------------
__device__ __forceinline__ unsigned long long pack2(float lo, float hi) {
    unsigned long long r;
    asm("mov.b64 %0, {%1, %2};" : "=l"(r) : "f"(lo), "f"(hi));
    return r;
}
__device__ __forceinline__ void ffma2(unsigned long long& d,
                                      unsigned long long a,
                                      unsigned long long b) {
    asm("fma.rn.f32x2 %0, %1, %2, %0;" : "+l"(d) : "l"(a), "l"(b));
}

// ---------------- GEMM: gates = h @ Wc^T (f32x2 FMA) ----------------
__global__ void __launch_bounds__(256) gemm_gates_kernel() {
    __shared__ float As[2][16][128];
    __shared__ float Bs[2][16][64];

    int tid = threadIdx.x;
    int tx  = tid & 15;
    int ty  = tid >> 4;
    int mb  = blockIdx.y * 128;
    int nb  = blockIdx.x * 64;

    int a_r0 = tid >> 2,  a_k = tid & 3;
    int a_r1 = (tid + 256) >> 2;
    int b_r  = tid >> 2,  b_k = tid & 3;

    unsigned long long acc[4][4];
    #pragma unroll
    for (int p = 0; p < 4; ++p)
        #pragma unroll
        for (int j = 0; j < 4; ++j) acc[p][j] = 0ull;

    float4 av0, av1, bv;
    av0 = *(const float4*)&g_h [(size_t)(mb + a_r0) * H + a_k * 4];
    av1 = *(const float4*)&g_h [(size_t)(mb + a_r1) * H + a_k * 4];
    bv  = *(const float4*)&g_Wc[(size_t)(nb + b_r ) * H + b_k * 4];
    {
        As[0][a_k*4+0][a_r0] = av0.x; As[0][a_k*4+1][a_r0] = av0.y;
        As[0][a_k*4+2][a_r0] = av0.z; As[0][a_k*4+3][a_r0] = av0.w;
        As[0][a_k*4+0][a_r1] = av1.x; As[0][a_k*4+1][a_r1] = av1.y;
        As[0][a_k*4+2][a_r1] = av1.z; As[0][a_k*4+3][a_r1] = av1.w;
        Bs[0][b_k*4+0][b_r]  = bv.x;  Bs[0][b_k*4+1][b_r]  = bv.y;
        Bs[0][b_k*4+2][b_r]  = bv.z;  Bs[0][b_k*4+3][b_r]  = bv.w;
    }
    __syncthreads();

    const int NS = H / 16;
    for (int s = 0; s < NS; ++s) {
        int buf = s & 1;
        if (s + 1 < NS) {
            int kk = (s + 1) * 16;
            av0 = *(const float4*)&g_h [(size_t)(mb + a_r0) * H + kk + a_k * 4];
            av1 = *(const float4*)&g_h [(size_t)(mb + a_r1) * H + kk + a_k * 4];
            bv  = *(const float4*)&g_Wc[(size_t)(nb + b_r ) * H + kk + b_k * 4];
        }
        #pragma unroll
        for (int k = 0; k < 16; ++k) {
            unsigned long long a2[4];
            #pragma unroll
            for (int p = 0; p < 4; ++p)
                a2[p] = *(const unsigned long long*)&As[buf][k][ty * 8 + 2 * p];
            float4 b4 = *(const float4*)&Bs[buf][k][tx * 4];
            unsigned long long b2[4];
            b2[0] = pack2(b4.x, b4.x); b2[1] = pack2(b4.y, b4.y);
            b2[2] = pack2(b4.z, b4.z); b2[3] = pack2(b4.w, b4.w);
            #pragma unroll
            for (int p = 0; p < 4; ++p)
                #pragma unroll
                for (int j = 0; j < 4; ++j)
                    ffma2(acc[p][j], a2[p], b2[j]);
        }
        if (s + 1 < NS) {
            int nbuf = 1 - buf;
            As[nbuf][a_k*4+0][a_r0] = av0.x; As[nbuf][a_k*4+1][a_r0] = av0.y;
            As[nbuf][a_k*4+2][a_r0] = av0.z; As[nbuf][a_k*4+3][a_r0] = av0.w;
            As[nbuf][a_k*4+0][a_r1] = av1.x; As[nbuf][a_k*4+1][a_r1] = av1.y;
            As[nbuf][a_k*4+2][a_r1] = av1.z; As[nbuf][a_k*4+3][a_r1] = av1.w;
            Bs[nbuf][b_k*4+0][b_r]  = bv.x;  Bs[nbuf][b_k*4+1][b_r]  = bv.y;
            Bs[nbuf][b_k*4+2][b_r]  = bv.z;  Bs[nbuf][b_k*4+3][b_r]  = bv.w;
        }
        __syncthreads();
    }

    #pragma unroll
    for (int p = 0; p < 4; ++p) {
        float lo[4], hi[4];
        #pragma unroll
        for (int j = 0; j < 4; ++j) {
            union { unsigned long long u; float2 f; } cv;
            cv.u = acc[p][j];
            lo[j] = cv.f.x; hi[j] = cv.f.y;
        }
        int m0 = mb + ty * 8 + 2 * p;
        *(float4*)&g_gates[(size_t)m0       * FOURH + nb + tx * 4] =
            make_float4(lo[0], lo[1], lo[2], lo[3]);
        *(float4*)&g_gates[(size_t)(m0 + 1) * FOURH + nb + tx * 4] =
            make_float4(hi[0], hi[1], hi[2], hi[3]);
    }
}

// ---------------- persistent fused attention ----------------
// x tile lifetime = scores phase only (values kept in registers for the
// weighted sum) -> next graph's TMA issues right after scores, overlapping
// softmax + wsum + reduce + next LSTM pointwise. 2 CTAs per SM.
//
// SMEM floats: xs[16384] | part[16][256] | qs[256] | sc[64] | redhi[256]
#define ATT_FLOATS (APG*H + 16*H + H + APG + H)
#define ATT_SMEM   (ATT_FLOATS*4 + 8)

__global__ void __launch_bounds__(512, 2) attn_kernel(const float* __restrict__ x,
                                                      float* __restrict__ out,
                                                      int mode) {
    extern __shared__ __align__(16) unsigned char smraw[];
    float* xs    = (float*)smraw;              // [64][256]
    float* part  = xs + APG * H;               // [16][256]
    float* qs    = part + 16 * H;              // [256]
    float* sc    = qs + H;                     // [64]
    float* redhi = sc + APG;                   // [256]
    uint32_t smem_base;
    asm("{ .reg .u64 t; cvta.to.shared.u64 t, %1; cvt.u32.u64 %0, t; }"
        : "=r"(smem_base) : "l"(smraw));
    uint32_t mbar  = smem_base + ATT_FLOATS * 4;
    uint32_t xs_sm = smem_base;

    int tid  = threadIdx.x;
    int lane = tid & 31;
    int w    = tid >> 5;

    if (tid == 0)
        asm volatile("mbarrier.init.shared.b64 [%0], 1;" :: "r"(mbar) : "memory");
    __syncthreads();

    // prologue: load first tile
    if (blockIdx.x < NG && tid == 0) {
        asm volatile("mbarrier.arrive.expect_tx.shared.b64 _, [%0], %1;"
                     :: "r"(mbar), "r"(TILE_B) : "memory");
        asm volatile("cp.async.bulk.shared::cta.global.mbarrier::complete_tx::bytes "
                     "[%0], [%1], %2, [%3];"
                     :: "r"(xs_sm), "l"(x + (size_t)blockIdx.x * APG * H),
                        "r"(TILE_B), "r"(mbar) : "memory");
    }

    int ph = 0;
    for (int b = blockIdx.x; b < NG; b += GRIDA) {
        // fused LSTM pointwise -> q (overlaps in-flight TMA)
        if (tid < H) {
            int j = tid;
            float q;
            if (mode == 0) {
                q = g_q0[j];
            } else {
                const float* gr = g_gates + (size_t)b * FOURH;
                float gi = gr[j]       + g_bc[j];
                float gf = gr[256 + j] + g_bc[256 + j];
                float gg = gr[512 + j] + g_bc[512 + j];
                float go = gr[768 + j] + g_bc[768 + j];
                float cp = (mode == 1) ? g_c0[j] : g_c[(size_t)b * H + j];
                float c  = sigmoidf_(gf) * cp + sigmoidf_(gi) * tanhf(gg);
                q = sigmoidf_(go) * tanhf(c);
                if (mode == 1) g_c[(size_t)b * H + j] = c;
                if (mode == 2) out[(size_t)b * (2 * H) + j] = q;
            }
            qs[j] = q;
        }

        // wait tile
        {
            uint32_t done;
            do {
                asm volatile(
                    "{ .reg .pred p; "
                    "mbarrier.try_wait.parity.acquire.cta.shared::cta.b64 p, [%1], %2, 0x989680; "
                    "selp.b32 %0, 1, 0, p; }"
                    : "=r"(done) : "r"(mbar), "r"(ph) : "memory");
            } while (!done);
            ph ^= 1;
        }
        __syncthreads();   // tile + qs visible

        // ---- scores: warp w -> atoms 4w..4w+3; x kept in registers ----
        // features: 4*lane..4*lane+3 and 128+4*lane..+3 (two float4 per row)
        float4 q4a = *(const float4*)&qs[4 * lane];
        float4 q4b = *(const float4*)&qs[128 + 4 * lane];
        float4 xr[4][2];
        #pragma unroll
        for (int aa = 0; aa < 4; ++aa) {
            const float* row = xs + (w * 4 + aa) * H;
            xr[aa][0] = *(const float4*)&row[4 * lane];
            xr[aa][1] = *(const float4*)&row[128 + 4 * lane];
            float p = xr[aa][0].x * q4a.x + xr[aa][0].y * q4a.y
                    + xr[aa][0].z * q4a.z + xr[aa][0].w * q4a.w
                    + xr[aa][1].x * q4b.x + xr[aa][1].y * q4b.y
                    + xr[aa][1].z * q4b.z + xr[aa][1].w * q4b.w;
            #pragma unroll
            for (int off = 16; off; off >>= 1)
                p += __shfl_xor_sync(0xffffffffu, p, off);
            if (lane == 0) sc[w * 4 + aa] = p;
        }
        __syncthreads();   // xs fully consumed; sc complete

        // ---- prefetch next graph into the SAME buffer ----
        int nxt = b + GRIDA;
        if (nxt < NG && tid == 0) {
            asm volatile("mbarrier.arrive.expect_tx.shared.b64 _, [%0], %1;"
                         :: "r"(mbar), "r"(TILE_B) : "memory");
            asm volatile("cp.async.bulk.shared::cta.global.mbarrier::complete_tx::bytes "
                         "[%0], [%1], %2, [%3];"
                         :: "r"(xs_sm), "l"(x + (size_t)nxt * APG * H),
                            "r"(TILE_B), "r"(mbar) : "memory");
        }

        // ---- softmax over 64 (warp 0) ----
        if (w == 0) {
            float v0 = sc[lane], v1 = sc[lane + 32];
            float mx = fmaxf(v0, v1);
            #pragma unroll
            for (int off = 16; off; off >>= 1)
                mx = fmaxf(mx, __shfl_xor_sync(0xffffffffu, mx, off));
            float e0 = __expf(v0 - mx), e1 = __expf(v1 - mx);
            float s = e0 + e1;
            #pragma unroll
            for (int off = 16; off; off >>= 1)
                s += __shfl_xor_sync(0xffffffffu, s, off);
            float inv = 1.0f / s;
            sc[lane]      = e0 * inv;
            sc[lane + 32] = e1 * inv;
        }
        __syncthreads();

        // ---- weighted sum from registers: per-warp partials ----
        {
            float a0 = sc[w * 4 + 0], a1 = sc[w * 4 + 1];
            float a2 = sc[w * 4 + 2], a3 = sc[w * 4 + 3];
            float4 p0, p1;
            p0.x = a0*xr[0][0].x + a1*xr[1][0].x + a2*xr[2][0].x + a3*xr[3][0].x;
            p0.y = a0*xr[0][0].y + a1*xr[1][0].y + a2*xr[2][0].y + a3*xr[3][0].y;
            p0.z = a0*xr[0][0].z + a1*xr[1][0].z + a2*xr[2][0].z + a3*xr[3][0].z;
            p0.w = a0*xr[0][0].w + a1*xr[1][0].w + a2*xr[2][0].w + a3*xr[3][0].w;
            p1.x = a0*xr[0][1].x + a1*xr[1][1].x + a2*xr[2][1].x + a3*xr[3][1].x;
            p1.y = a0*xr[0][1].y + a1*xr[1][1].y + a2*xr[2][1].y + a3*xr[3][1].y;
            p1.z = a0*xr[0][1].z + a1*xr[1][1].z + a2*xr[2][1].z + a3*xr[3][1].z;
            p1.w = a0*xr[0][1].w + a1*xr[1][1].w + a2*xr[2][1].w + a3*xr[3][1].w;
            *(float4*)&part[w * H + 4 * lane]       = p0;
            *(float4*)&part[w * H + 128 + 4 * lane] = p1;
        }
        __syncthreads();

        // ---- cross-warp reduce: threads 0..255 sum warps 0..7,
        //      threads 256..511 sum warps 8..15 ----
        {
            int f    = tid & (H - 1);
            int half = tid >> 8;
            const float* pp = part + half * 8 * H + f;
            float s = pp[0] + pp[H] + pp[2*H] + pp[3*H]
                    + pp[4*H] + pp[5*H] + pp[6*H] + pp[7*H];
            if (half) {
                redhi[f] = s;
            }
            __syncthreads();
            if (!half) {
                float rr = s + redhi[f];
                g_h[(size_t)b * H + f] = rr;
                if (mode == 2) out[(size_t)b * (2 * H) + H + f] = rr;
            }
        }
        __syncthreads();   // part/redhi reuse safe next iteration
    }
}

// ---------------- launch ----------------
extern "C" void kernel_launch(void* const* d_in, const int* in_sizes, int n_in,
                              void* d_out, int out_size) {
    const float* x    = (const float*)d_in[0];
    const float* W_ih = (const float*)d_in[3];
    const float* W_hh = (const float*)d_in[4];
    const float* b_ih = (const float*)d_in[5];
    const float* b_hh = (const float*)d_in[6];
    float* out = (float*)d_out;

    cudaFuncSetAttribute(attn_kernel,
                         cudaFuncAttributeMaxDynamicSharedMemorySize,
                         (int)ATT_SMEM);

    prep_kernel<<<1024, 256>>>(W_ih, W_hh, b_ih, b_hh);

    dim3 ggrid(FOURH / 64, NG / 128);

    attn_kernel<<<GRIDA, 512, ATT_SMEM>>>(x, nullptr, 0);   // step 0
    gemm_gates_kernel<<<ggrid, 256>>>();
    attn_kernel<<<GRIDA, 512, ATT_SMEM>>>(x, nullptr, 1);   // step 1
    gemm_gates_kernel<<<ggrid, 256>>>();
    attn_kernel<<<GRIDA, 512, ATT_SMEM>>>(x, out, 2);       // step 2
}

// round 5
// speedup vs baseline: 1.1554x; 1.1554x over previous
#include <cuda_runtime.h>
#include <cstdint>

#define H        256
#define NG       2048
#define APG      64
#define GRID     148
#define TILE_F   (APG*H)       // 16384 floats per graph tile
#define TILE_B   (TILE_F*4)    // 65536 bytes
#define GMAX     14

// ---------------- device globals ----------------
__device__ float4 g_WcT4[64 * 1024];   // [kc][n] = (W_ih+W_hh)[n][4kc..4kc+3]
__device__ float  g_bc[1024];          // b_ih + b_hh
__device__ float  g_q0[H];
__device__ float  g_c0[H];

__device__ __forceinline__ float sigmoidf_(float v) {
    return 1.0f / (1.0f + __expf(-v));
}

// ---------------- prep: fold + transpose weights, step-0 state ----------------
__global__ void prep_kernel(const float* __restrict__ W_ih,
                            const float* __restrict__ W_hh,
                            const float* __restrict__ b_ih,
                            const float* __restrict__ b_hh) {
    int idx = blockIdx.x * 256 + threadIdx.x;    // 65536 threads
    int kc = idx >> 10, n = idx & 1023;
    float4 a = *(const float4*)&W_ih[n * H + kc * 4];
    float4 b = *(const float4*)&W_hh[n * H + kc * 4];
    g_WcT4[idx] = make_float4(a.x + b.x, a.y + b.y, a.z + b.z, a.w + b.w);
    if (idx < 1024) g_bc[idx] = b_ih[idx] + b_hh[idx];
    if (idx < H) {
        float gi = b_ih[idx]       + b_hh[idx];
        float gg = b_ih[512 + idx] + b_hh[512 + idx];
        float go = b_ih[768 + idx] + b_hh[768 + idx];
        float c  = sigmoidf_(gi) * tanhf(gg);
        g_c0[idx] = c;
        g_q0[idx] = sigmoidf_(go) * tanhf(c);
    }
}

// ---------------- packed f32x2 helpers ----------------
__device__ __forceinline__ unsigned long long pack2(float lo, float hi) {
    unsigned long long r;
    asm("mov.b64 %0, {%1, %2};" : "=l"(r) : "f"(lo), "f"(hi));
    return r;
}
__device__ __forceinline__ void ffma2(unsigned long long& d,
                                      unsigned long long a,
                                      unsigned long long b) {
    asm("fma.rn.f32x2 %0, %1, %2, %0;" : "+l"(d) : "l"(a), "l"(b));
}
__device__ __forceinline__ float2 unpack2(unsigned long long v) {
    union { unsigned long long u; float2 f; } cv; cv.u = v; return cv.f;
}

// ---------------- SMEM layout (floats) ----------------
// xs  [2][16384]  = 32768
// hp  [7][256]x2  =  3584   (graph-pair packed h, float2 per (pair,k))
// cst [14][256]   =  3584
// qst [14][256]   =  3584
// fo  [2][7][256]x2 = 7168  (f-gate, o-gate exchange, float2)
// sc  [64]
// red [1024]                (float2 partials, 512 threads)
#define SM_FLOATS (32768 + 3584 + 3584 + 3584 + 7168 + 64 + 1024)
#define SM_BYTES  (SM_FLOATS * 4 + 16)

__global__ void __launch_bounds__(512, 1)
fused_kernel(const float* __restrict__ x, float* __restrict__ out) {
    extern __shared__ __align__(16) unsigned char smraw[];
    float* xs  = (float*)smraw;
    float* hp  = xs  + 2 * TILE_F;
    float* cst = hp  + 3584;
    float* qst = cst + GMAX * H;
    float* fo  = qst + GMAX * H;          // fo_f = fo, fo_o = fo + 3584
    float* sc  = fo  + 7168;
    float* red = sc  + 64;

    uint32_t smem_base;
    asm("{ .reg .u64 t; cvta.to.shared.u64 t, %1; cvt.u32.u64 %0, t; }"
        : "=r"(smem_base) : "l"(smraw));
    uint32_t mb0 = smem_base + SM_FLOATS * 4;
    uint32_t mb1 = mb0 + 8;

    int tid  = threadIdx.x;
    int lane = tid & 31;
    int w    = tid >> 5;
    int bid  = blockIdx.x;
    int G    = (NG - bid + GRID - 1) / GRID;   // 13 or 14
    int total = 3 * G;

    // init SMEM state
    for (int idx = tid; idx < 3584; idx += 512) hp[idx] = 0.0f;
    for (int idx = tid; idx < GMAX * H; idx += 512) {
        cst[idx] = g_c0[idx & (H - 1)];
        qst[idx] = g_q0[idx & (H - 1)];
    }
    if (tid == 0) {
        asm volatile("mbarrier.init.shared.b64 [%0], 1;" :: "r"(mb0) : "memory");
        asm volatile("mbarrier.init.shared.b64 [%0], 1;" :: "r"(mb1) : "memory");
    }
    __syncthreads();

    // per-thread biases (threads < 256)
    float bci = 0, bcf = 0, bcg = 0, bco = 0;
    if (tid < H) {
        bci = g_bc[tid];       bcf = g_bc[256 + tid];
        bcg = g_bc[512 + tid]; bco = g_bc[768 + tid];
    }

    // issue consumption-slot j's TMA load
    auto issue = [&](int j) {
        if (j < total && tid == 0) {
            int i2 = j % G;
            size_t g = (size_t)bid + (size_t)GRID * i2;
            uint32_t mbj = (j & 1) ? mb1 : mb0;
            uint32_t dst = smem_base + (uint32_t)(j & 1) * TILE_B;
            asm volatile("mbarrier.arrive.expect_tx.shared.b64 _, [%0], %1;"
                         :: "r"(mbj), "r"(TILE_B) : "memory");
            asm volatile("cp.async.bulk.shared::cta.global.mbarrier::complete_tx::bytes "
                         "[%0], [%1], %2, [%3];"
                         :: "r"(dst), "l"(x + g * TILE_F), "r"(TILE_B), "r"(mbj)
                         : "memory");
        }
    };
    issue(0); issue(1);

    int ph0 = 0, ph1 = 0;
    int jj = 0;
    for (int s = 0; s < 3; ++s) {
        // ================= mat-vec + LSTM pointwise =================
        if (s > 0) {
            unsigned long long acc1[7], acc2[7];
            #pragma unroll
            for (int p = 0; p < 7; ++p) { acc1[p] = 0ull; acc2[p] = 0ull; }

            for (int kc = 0; kc < 64; ++kc) {
                float4 w1 = g_WcT4[kc * 1024 + tid];
                float4 w2 = g_WcT4[kc * 1024 + 512 + tid];
                unsigned long long w1x = pack2(w1.x, w1.x), w1y = pack2(w1.y, w1.y);
                unsigned long long w1z = pack2(w1.z, w1.z), w1w = pack2(w1.w, w1.w);
                unsigned long long w2x = pack2(w2.x, w2.x), w2y = pack2(w2.y, w2.y);
                unsigned long long w2z = pack2(w2.z, w2.z), w2w = pack2(w2.w, w2.w);
                #pragma unroll
                for (int p = 0; p < 7; ++p) {
                    ulonglong2 hA = *(const ulonglong2*)&hp[(p * 256 + kc * 4) * 2];
                    ulonglong2 hB = *(const ulonglong2*)&hp[(p * 256 + kc * 4 + 2) * 2];
                    ffma2(acc1[p], hA.x, w1x); ffma2(acc2[p], hA.x, w2x);
                    ffma2(acc1[p], hA.y, w1y); ffma2(acc2[p], hA.y, w2y);
                    ffma2(acc1[p], hB.x, w1z); ffma2(acc2[p], hB.x, w2z);
                    ffma2(acc1[p], hB.y, w1w); ffma2(acc2[p], hB.y, w2w);
                }
            }
            // exchange f/o gates (threads >= 256 hold n=t (f), n=t+512 (o))
            if (tid >= 256) {
                int f = tid - 256;
                #pragma unroll
                for (int p = 0; p < 7; ++p) {
                    *(unsigned long long*)&fo[(p * 256 + f) * 2]        = acc1[p];
                    *(unsigned long long*)&fo[3584 + (p * 256 + f) * 2] = acc2[p];
                }
            }
            __syncthreads();
            // pointwise (threads < 256 hold n=t (i), n=t+512 (g))
            if (tid < H) {
                #pragma unroll
                for (int p = 0; p < 7; ++p) {
                    float2 iv = unpack2(acc1[p]);
                    float2 gv = unpack2(acc2[p]);
                    float2 fv = *(const float2*)&fo[(p * 256 + tid) * 2];
                    float2 ov = *(const float2*)&fo[3584 + (p * 256 + tid) * 2];
                    #pragma unroll
                    for (int l = 0; l < 2; ++l) {
                        int i = 2 * p + l;
                        if (i >= G) continue;
                        float gi = (l ? iv.y : iv.x) + bci;
                        float gf = (l ? fv.y : fv.x) + bcf;
                        float gg = (l ? gv.y : gv.x) + bcg;
                        float go = (l ? ov.y : ov.x) + bco;
                        float cold = cst[i * H + tid];
                        float cn = sigmoidf_(gf) * cold + sigmoidf_(gi) * tanhf(gg);
                        float qn = sigmoidf_(go) * tanhf(cn);
                        cst[i * H + tid] = cn;
                        qst[i * H + tid] = qn;
                        if (s == 2) {
                            size_t g = (size_t)bid + (size_t)GRID * i;
                            out[g * (2 * H) + tid] = qn;
                        }
                    }
                }
            }
            __syncthreads();
        }

        // ================= attention over this CTA's graphs =================
        for (int i = 0; i < G; ++i, ++jj) {
            int buf = jj & 1;
            // wait for tile
            {
                uint32_t mbc = buf ? mb1 : mb0;
                int phc = buf ? ph1 : ph0;
                uint32_t done;
                do {
                    asm volatile(
                        "{ .reg .pred p; "
                        "mbarrier.try_wait.parity.acquire.cta.shared::cta.b64 p, [%1], %2, 0x989680; "
                        "selp.b32 %0, 1, 0, p; }"
                        : "=r"(done) : "r"(mbc), "r"(phc) : "memory");
                } while (!done);
                if (buf) ph1 ^= 1; else ph0 ^= 1;
            }
            __syncthreads();

            const float* X    = xs + buf * TILE_F;
            const float* qrow = qst + i * H;

            // scores: warp w -> atoms 4w..4w+3
            float4 q4a = *(const float4*)&qrow[4 * lane];
            float4 q4b = *(const float4*)&qrow[128 + 4 * lane];
            #pragma unroll
            for (int aa = 0; aa < 4; ++aa) {
                const float* row = X + (w * 4 + aa) * H;
                float4 xa = *(const float4*)&row[4 * lane];
                float4 xb = *(const float4*)&row[128 + 4 * lane];
                float p = xa.x * q4a.x + xa.y * q4a.y + xa.z * q4a.z + xa.w * q4a.w
                        + xb.x * q4b.x + xb.y * q4b.y + xb.z * q4b.z + xb.w * q4b.w;
                #pragma unroll
                for (int off = 16; off; off >>= 1)
                    p += __shfl_xor_sync(0xffffffffu, p, off);
                if (lane == 0) sc[w * 4 + aa] = p;
            }
            __syncthreads();

            // softmax over 64 (warp 0)
            if (w == 0) {
                float v0 = sc[lane], v1 = sc[lane + 32];
                float mx = fmaxf(v0, v1);
                #pragma unroll
                for (int off = 16; off; off >>= 1)
                    mx = fmaxf(mx, __shfl_xor_sync(0xffffffffu, mx, off));
                float e0 = __expf(v0 - mx), e1 = __expf(v1 - mx);
                float ssum = e0 + e1;
                #pragma unroll
                for (int off = 16; off; off >>= 1)
                    ssum += __shfl_xor_sync(0xffffffffu, ssum, off);
                float inv = 1.0f / ssum;
                sc[lane]      = e0 * inv;
                sc[lane + 32] = e1 * inv;
            }
            __syncthreads();

            // weighted sum: thread -> feature pair (2*jq, 2*jq+1), quarter of atoms
            {
                int jq = tid & 127;
                int qt = tid >> 7;
                float2 r2 = make_float2(0.0f, 0.0f);
                const float* Xq = X + qt * 16 * H + 2 * jq;
                #pragma unroll
                for (int a0 = 0; a0 < 16; ++a0) {
                    float sw = sc[qt * 16 + a0];
                    float2 xv = *(const float2*)&Xq[a0 * H];
                    r2.x = fmaf(sw, xv.x, r2.x);
                    r2.y = fmaf(sw, xv.y, r2.y);
                }
                *(float2*)&red[tid * 2] = r2;
            }
            __syncthreads();
            if (tid < 128) {
                float2 r0 = *(const float2*)&red[tid * 2];
                float2 r1 = *(const float2*)&red[(tid + 128) * 2];
                float2 r2 = *(const float2*)&red[(tid + 256) * 2];
                float2 r3 = *(const float2*)&red[(tid + 384) * 2];
                float2 rr = make_float2(r0.x + r1.x + r2.x + r3.x,
                                        r0.y + r1.y + r2.y + r3.y);
                int p = i >> 1, l = i & 1;
                hp[(p * 256 + 2 * tid)     * 2 + l] = rr.x;
                hp[(p * 256 + 2 * tid + 1) * 2 + l] = rr.y;
                if (s == 2) {
                    size_t g = (size_t)bid + (size_t)GRID * i;
                    *(float2*)&out[g * (2 * H) + H + 2 * tid] = rr;
                }
            }
            __syncthreads();   // X + hp writes complete

            issue(jj + 2);     // refill this buffer (next consumer is jj+2)
        }
    }
}

// ---------------- launch ----------------
extern "C" void kernel_launch(void* const* d_in, const int* in_sizes, int n_in,
                              void* d_out, int out_size) {
    const float* x    = (const float*)d_in[0];
    const float* W_ih = (const float*)d_in[3];
    const float* W_hh = (const float*)d_in[4];
    const float* b_ih = (const float*)d_in[5];
    const float* b_hh = (const float*)d_in[6];
    float* out = (float*)d_out;

    cudaFuncSetAttribute(fused_kernel,
                         cudaFuncAttributeMaxDynamicSharedMemorySize,
                         (int)SM_BYTES);

    prep_kernel<<<256, 256>>>(W_ih, W_hh, b_ih, b_hh);
    fused_kernel<<<GRID, 512, SM_BYTES>>>(x, out);
}